// round 1
// baseline (speedup 1.0000x reference)
#include <cuda_runtime.h>
#include <math.h>

#define N_ITERS 12
#define NB 4
#define NH 384
#define NW 512
#define HW (NH * NW)
#define NC 3

// Scratch: frame1 interleaved as [B, H, W] of float4 (c0,c1,c2,0). 12.6 MB.
__device__ float4 g_f1i[NB * HW];
// Per-iteration SSE accumulators.
__device__ float g_sums[N_ITERS];

// Prolog: interleave frame1 channels into float4 layout + zero accumulators.
__global__ void interleave_kernel(const float* __restrict__ f1) {
    int idx = blockIdx.x * blockDim.x + threadIdx.x;
    if (blockIdx.x == 0 && threadIdx.x < N_ITERS) g_sums[threadIdx.x] = 0.0f;
    if (idx < NB * HW) {
        int b = idx / HW;
        int p = idx - b * HW;
        const float* base = f1 + (size_t)b * 3 * HW + p;
        float4 v;
        v.x = base[0];
        v.y = base[HW];
        v.z = base[2 * HW];
        v.w = 0.0f;
        g_f1i[idx] = v;
    }
}

// Main: one thread per pixel (b,h,w); all 12 iterations fused so frame2 stays
// in registers and frame1 gathers hit L1.
__global__ __launch_bounds__(256) void warp_psnr_kernel(
    const float* __restrict__ flow, const float* __restrict__ frame2)
{
    const int pix = blockIdx.x * 256 + threadIdx.x;   // 0..HW-1
    const int b = blockIdx.y;
    const int h = pix >> 9;        // W = 512
    const int w = pix & 511;
    const float hf = (float)h, wf = (float)w;

    const float* f2 = frame2 + (size_t)b * 3 * HW + pix;
    const float r2x = f2[0];
    const float r2y = f2[HW];
    const float r2z = f2[2 * HW];

    const float4* __restrict__ f1b = g_f1i + b * HW;
    const float* flp = flow + (size_t)b * 2 * HW + pix;

    float sums[N_ITERS];

    #pragma unroll
    for (int i = 0; i < N_ITERS; i++) {
        const float fy = flp[0];
        const float fx = flp[HW];
        flp += (size_t)NB * 2 * HW;

        const float px = wf + fx;
        const float py = hf + fy;
        const float x0f = floorf(px);
        const float y0f = floorf(py);
        const float wx1 = px - x0f;
        const float wy1 = py - y0f;
        const float wx0 = 1.0f - wx1;
        const float wy0 = 1.0f - wy1;

        const int x0 = (int)x0f;
        const int y0 = (int)y0f;
        const int x1 = x0 + 1;
        const int y1 = y0 + 1;

        const bool vx0 = (unsigned)x0 < (unsigned)NW;
        const bool vx1 = (unsigned)x1 < (unsigned)NW;
        const bool vy0 = (unsigned)y0 < (unsigned)NH;
        const bool vy1 = (unsigned)y1 < (unsigned)NH;

        const int x0c = min(max(x0, 0), NW - 1);
        const int x1c = min(max(x1, 0), NW - 1);
        const int y0c = min(max(y0, 0), NH - 1);
        const int y1c = min(max(y1, 0), NH - 1);

        const float4* r0 = f1b + y0c * NW;
        const float4* r1 = f1b + y1c * NW;
        const float4 f00 = r0[x0c];
        const float4 f01 = r0[x1c];
        const float4 f10 = r1[x0c];
        const float4 f11 = r1[x1c];

        const float w00 = (vy0 && vx0) ? wy0 * wx0 : 0.0f;
        const float w01 = (vy0 && vx1) ? wy0 * wx1 : 0.0f;
        const float w10 = (vy1 && vx0) ? wy1 * wx0 : 0.0f;
        const float w11 = (vy1 && vx1) ? wy1 * wx1 : 0.0f;

        const float ex = f00.x * w00 + f01.x * w01 + f10.x * w10 + f11.x * w11;
        const float ey = f00.y * w00 + f01.y * w01 + f10.y * w10 + f11.y * w11;
        const float ez = f00.z * w00 + f01.z * w01 + f10.z * w10 + f11.z * w11;

        const float dx = ex - r2x;
        const float dy = ey - r2y;
        const float dz = ez - r2z;
        sums[i] = fmaf(dx, dx, fmaf(dy, dy, dz * dz));
    }

    // Block reduction: warp shuffle -> shared -> 12 atomics per block.
    __shared__ float red[N_ITERS][8];
    const int lane = threadIdx.x & 31;
    const int wid = threadIdx.x >> 5;

    #pragma unroll
    for (int i = 0; i < N_ITERS; i++) {
        float s = sums[i];
        s += __shfl_down_sync(0xffffffffu, s, 16);
        s += __shfl_down_sync(0xffffffffu, s, 8);
        s += __shfl_down_sync(0xffffffffu, s, 4);
        s += __shfl_down_sync(0xffffffffu, s, 2);
        s += __shfl_down_sync(0xffffffffu, s, 1);
        if (lane == 0) red[i][wid] = s;
    }
    __syncthreads();

    if (threadIdx.x < N_ITERS) {
        float t = 0.0f;
        #pragma unroll
        for (int ww = 0; ww < 8; ww++) t += red[threadIdx.x][ww];
        atomicAdd(&g_sums[threadIdx.x], t);
    }
}

// Epilog: PSNRs, cascading weights, final scalar loss.
__global__ void loss_kernel(float* __restrict__ out) {
    if (threadIdx.x == 0 && blockIdx.x == 0) {
        const float inv_n = 1.0f / (float)(NB * NC * HW);
        float loss = 0.0f;
        #pragma unroll
        for (int i = 0; i < N_ITERS; i++) {
            const float mse = g_sums[i] * inv_n;
            const float psnr = -10.0f * log10f(mse);
            const float wgt = powf(0.85f, (float)(N_ITERS - i));
            loss += psnr * wgt;
        }
        out[0] = -loss;
    }
}

extern "C" void kernel_launch(void* const* d_in, const int* in_sizes, int n_in,
                              void* d_out, int out_size) {
    const float* flow   = (const float*)d_in[0];  // [12,4,2,384,512]
    const float* frame1 = (const float*)d_in[1];  // [4,3,384,512]
    const float* frame2 = (const float*)d_in[2];  // [4,3,384,512]
    float* out = (float*)d_out;

    (void)in_sizes; (void)n_in; (void)out_size;

    const int threads = 256;
    interleave_kernel<<<(NB * HW + threads - 1) / threads, threads>>>(frame1);

    dim3 grid(HW / threads, NB);
    warp_psnr_kernel<<<grid, threads>>>(flow, frame2);

    loss_kernel<<<1, 32>>>(out);
}

// round 2
// speedup vs baseline: 1.0640x; 1.0640x over previous
#include <cuda_runtime.h>
#include <math.h>

#define N_ITERS 12
#define NB 4
#define NH 384
#define NW 512
#define HW (NH * NW)

#define BLK_W 32
#define BLK_H 16
#define HALO 8
#define TILE_W (BLK_W + 2 * HALO)   // 48
#define TILE_H (BLK_H + 2 * HALO)   // 32
#define TILE_STRIDE (TILE_W + 1)    // 49 float4 -> decorrelate banks

__device__ float g_sums[N_ITERS];

__global__ void init_kernel() {
    if (threadIdx.x < N_ITERS) g_sums[threadIdx.x] = 0.0f;
}

// Global-memory bilinear fallback (only taken if a sample escapes the halo;
// statistically never for N(0,1) flow, but kept for correctness robustness).
__device__ __noinline__ float3 global_bilinear(
    const float* __restrict__ f1b, int x0, int y0,
    float w00, float w01, float w10, float w11)
{
    const int x0c = min(max(x0, 0), NW - 1);
    const int x1c = min(max(x0 + 1, 0), NW - 1);
    const int y0c = min(max(y0, 0), NH - 1);
    const int y1c = min(max(y0 + 1, 0), NH - 1);
    float3 r;
    float* rp = &r.x;
    #pragma unroll
    for (int c = 0; c < 3; c++) {
        const float* p = f1b + c * HW;
        rp[c] = p[y0c * NW + x0c] * w00 + p[y0c * NW + x1c] * w01
              + p[y1c * NW + x0c] * w10 + p[y1c * NW + x1c] * w11;
    }
    return r;
}

__global__ __launch_bounds__(BLK_W * BLK_H, 2) void warp_psnr_kernel(
    const float* __restrict__ flow,
    const float* __restrict__ frame1,
    const float* __restrict__ frame2)
{
    __shared__ float4 tile[TILE_H * TILE_STRIDE];

    const int tx = threadIdx.x;
    const int ty = threadIdx.y;
    const int bx = blockIdx.x * BLK_W;
    const int by = blockIdx.y * BLK_H;
    const int b  = blockIdx.z;
    const int w = bx + tx;
    const int h = by + ty;
    const int tid = ty * BLK_W + tx;

    const float* __restrict__ f1b = frame1 + (size_t)b * 3 * HW;

    // ---- Fill frame1 tile (clamp-to-edge; clamped texels only ever pair with
    // zero weights, so contents outside the image are harmless). ----
    for (int t = tid; t < TILE_H * TILE_W; t += BLK_W * BLK_H) {
        const int r = t / TILE_W;
        const int c = t - r * TILE_W;
        const int gy = min(max(by - HALO + r, 0), NH - 1);
        const int gx = min(max(bx - HALO + c, 0), NW - 1);
        const int g = gy * NW + gx;
        float4 v;
        v.x = f1b[g];
        v.y = f1b[HW + g];
        v.z = f1b[2 * HW + g];
        v.w = 0.0f;
        tile[r * TILE_STRIDE + c] = v;
    }
    __syncthreads();

    // ---- frame2 pixel in registers for all 12 iterations ----
    const int pix = h * NW + w;
    const float* f2 = frame2 + (size_t)b * 3 * HW + pix;
    const float r2x = f2[0];
    const float r2y = f2[HW];
    const float r2z = f2[2 * HW];

    const float hf = (float)h, wf = (float)w;
    const float* flp = flow + (size_t)b * 2 * HW + pix;

    float sums[N_ITERS];

    #pragma unroll
    for (int i = 0; i < N_ITERS; i++) {
        const float fy = flp[0];
        const float fx = flp[HW];
        flp += (size_t)NB * 2 * HW;

        const float px = wf + fx;
        const float py = hf + fy;
        const float x0f = floorf(px);
        const float y0f = floorf(py);
        const float wx1 = px - x0f;
        const float wy1 = py - y0f;
        const float wx0 = 1.0f - wx1;
        const float wy0 = 1.0f - wy1;

        const int x0 = (int)x0f;
        const int y0 = (int)y0f;
        const int x1 = x0 + 1;
        const int y1 = y0 + 1;

        const bool vx0 = (unsigned)x0 < (unsigned)NW;
        const bool vx1 = (unsigned)x1 < (unsigned)NW;
        const bool vy0 = (unsigned)y0 < (unsigned)NH;
        const bool vy1 = (unsigned)y1 < (unsigned)NH;

        const float w00 = (vy0 && vx0) ? wy0 * wx0 : 0.0f;
        const float w01 = (vy0 && vx1) ? wy0 * wx1 : 0.0f;
        const float w10 = (vy1 && vx0) ? wy1 * wx0 : 0.0f;
        const float w11 = (vy1 && vx1) ? wy1 * wx1 : 0.0f;

        // tile-local coordinates
        const int sx = x0 - (bx - HALO);
        const int sy = y0 - (by - HALO);

        float ex, ey, ez;
        if (sx >= 0 && sx < TILE_W - 1 && sy >= 0 && sy < TILE_H - 1) {
            const float4* r0 = tile + sy * TILE_STRIDE + sx;
            const float4 f00 = r0[0];
            const float4 f01 = r0[1];
            const float4 f10 = r0[TILE_STRIDE];
            const float4 f11 = r0[TILE_STRIDE + 1];
            ex = f00.x * w00 + f01.x * w01 + f10.x * w10 + f11.x * w11;
            ey = f00.y * w00 + f01.y * w01 + f10.y * w10 + f11.y * w11;
            ez = f00.z * w00 + f01.z * w01 + f10.z * w10 + f11.z * w11;
        } else {
            const float3 e = global_bilinear(f1b, x0, y0, w00, w01, w10, w11);
            ex = e.x; ey = e.y; ez = e.z;
        }

        const float dx = ex - r2x;
        const float dy = ey - r2y;
        const float dz = ez - r2z;
        sums[i] = fmaf(dx, dx, fmaf(dy, dy, dz * dz));
    }

    // ---- Block reduction: warp shuffle -> shared -> 12 atomics ----
    __shared__ float red[N_ITERS][16];
    const int lane = tid & 31;
    const int wid  = tid >> 5;

    #pragma unroll
    for (int i = 0; i < N_ITERS; i++) {
        float s = sums[i];
        s += __shfl_down_sync(0xffffffffu, s, 16);
        s += __shfl_down_sync(0xffffffffu, s, 8);
        s += __shfl_down_sync(0xffffffffu, s, 4);
        s += __shfl_down_sync(0xffffffffu, s, 2);
        s += __shfl_down_sync(0xffffffffu, s, 1);
        if (lane == 0) red[i][wid] = s;
    }
    __syncthreads();

    if (tid < N_ITERS) {
        float t = 0.0f;
        #pragma unroll
        for (int ww = 0; ww < 16; ww++) t += red[tid][ww];
        atomicAdd(&g_sums[tid], t);
    }
}

__global__ void loss_kernel(float* __restrict__ out) {
    if (threadIdx.x == 0 && blockIdx.x == 0) {
        const float inv_n = 1.0f / (float)(NB * 3 * HW);
        float loss = 0.0f;
        #pragma unroll
        for (int i = 0; i < N_ITERS; i++) {
            const float mse = g_sums[i] * inv_n;
            const float psnr = -10.0f * log10f(mse);
            const float wgt = powf(0.85f, (float)(N_ITERS - i));
            loss += psnr * wgt;
        }
        out[0] = -loss;
    }
}

extern "C" void kernel_launch(void* const* d_in, const int* in_sizes, int n_in,
                              void* d_out, int out_size) {
    const float* flow   = (const float*)d_in[0];  // [12,4,2,384,512]
    const float* frame1 = (const float*)d_in[1];  // [4,3,384,512]
    const float* frame2 = (const float*)d_in[2];  // [4,3,384,512]
    float* out = (float*)d_out;
    (void)in_sizes; (void)n_in; (void)out_size;

    init_kernel<<<1, 32>>>();

    dim3 block(BLK_W, BLK_H);
    dim3 grid(NW / BLK_W, NH / BLK_H, NB);
    warp_psnr_kernel<<<grid, block>>>(flow, frame1, frame2);

    loss_kernel<<<1, 32>>>(out);
}